// round 15
// baseline (speedup 1.0000x reference)
#include <cuda_runtime.h>

// Problem constants (fixed shapes per reference)
#define B_    4
#define M_    1024
#define N_    1024
#define DX_   32
#define H_    32
#define DV_   64
#define NPAIR 16      // H_/2 pair-sums per row

#define XLA_TANH_CLAMP 7.99881172180175781f

typedef unsigned long long ull;

// Scratch (no cudaMalloc allowed)
__device__ __align__(16) ull   g_k2t[B_ * 8 * N_];      // TRANSPOSED k pair-sums: [b][i][n] (ull = pairs 2i,2i+1)
__device__ __align__(16) float g_q2n[B_ * M_ * NPAIR];  // NEGATED pair sums of q (row-major)
__device__ __align__(16) float g_kf [B_ * N_ * H_];     // full k projection
__device__ __align__(16) float g_qfn[B_ * M_ * H_];     // NEGATED full q projection
__device__ __align__(16) float g_Sp [B_ * 16 * DV_];    // partial sums of r over n (16/batch)

// ---------------------------------------------------------------------------
// XLA EmitFastTanh (f32, with_fma=true) — bit-faithful replica.
// ---------------------------------------------------------------------------
__device__ __forceinline__ float xla_fast_tanh(float x) {
    float xc = fminf(fmaxf(x, -XLA_TANH_CLAMP), XLA_TANH_CLAMP);
    float x2 = xc * xc;
    float p = fmaf(x2, -2.76076847742355e-16f, 2.00018790482477e-13f);
    p = fmaf(x2, p, -8.60467152213735e-11f);
    p = fmaf(x2, p, 5.12229709037114e-08f);
    p = fmaf(x2, p, 1.48572235717979e-05f);
    p = fmaf(x2, p, 6.37261928875436e-04f);
    p = fmaf(x2, p, 4.89352455891786e-03f);
    p = xc * p;
    float q = fmaf(x2, 1.19825839466702e-06f, 1.18534705686654e-04f);
    q = fmaf(x2, q, 2.26843463243900e-03f);
    q = fmaf(x2, q, 4.89352518554385e-03f);
    float t = p / q;                  // IEEE div.rn
    if (fabsf(x) < 0.0004f) t = x;
    return t;
}

// Packed f32x2 helpers
__device__ __forceinline__ ull add2(ull a, ull b) {
    ull d;
    asm("add.rn.f32x2 %0, %1, %2;" : "=l"(d) : "l"(a), "l"(b));
    return d;
}
__device__ __forceinline__ float hsum2(ull a) {
    float lo, hi;
    asm("mov.b64 {%0, %1}, %2;" : "=f"(lo), "=f"(hi) : "l"(a));
    return lo + hi;
}
__device__ __forceinline__ ull pk2(float lo, float hi) {
    ull r;
    asm("mov.b64 %0, {%1, %2};" : "=l"(r) : "f"(lo), "f"(hi));
    return r;
}
#define ABS2_MASK 0x7FFFFFFF7FFFFFFFULL

// ---------------------------------------------------------------------------
// prep: 320 blocks x 256 threads.  (EXACT R12 version — best measured)
//  blocks   0..63  : r column-sum partials (16/batch, 64 n each) -> g_Sp.
//  blocks  64..191 : k projections (x1), 32 rows/block -> g_kf + g_k2t
//                    (k2t via SMEM transpose -> coalesced STG.64).
//  blocks 192..319 : q projections NEGATED (x2), 32 rows/block -> g_qfn+g_q2n.
//  Ws padded to DX_+1: lane banks (2j+d) mod 32 are conflict-free.
// ---------------------------------------------------------------------------
__global__ __launch_bounds__(256) void prep_kernel(
    const float* __restrict__ x1,
    const float* __restrict__ x2,
    const float* __restrict__ r_in,
    const float* __restrict__ W,
    const float* __restrict__ bias
) {
    int blk = blockIdx.x, tid = threadIdx.x;

    if (blk < 64) {
        __shared__ float ps[4][DV_];
        int batch = blk >> 4, part = blk & 15;
        int v = tid & 63, sub = tid >> 6;           // 4 subs x 16 n
        const float* rp = r_in + ((size_t)batch * N_ + part * 64 + sub * 16) * DV_ + v;
        float s = 0.f;
        #pragma unroll
        for (int n = 0; n < 16; n++) s += rp[n * DV_];
        ps[sub][v] = s;
        __syncthreads();
        if (tid < DV_)
            g_Sp[((size_t)batch * 16 + part) * DV_ + tid] =
                (ps[0][tid] + ps[1][tid]) + (ps[2][tid] + ps[3][tid]);
        return;
    }

    __shared__ float  Ws[H_][DX_ + 1];
    __shared__ float  bs[H_];
    __shared__ float4 xs4[32 * (DX_ / 4)];
    __shared__ float  ktps[NPAIR][33];

    for (int i = tid; i < H_ * DX_; i += 256) {
        int h = i >> 5, d = i & 31;
        Ws[h][d] = W[i];
    }
    if (tid < H_) bs[tid] = bias[tid];

    int isq   = (blk >= 192);
    int lrow0 = ((blk - 64) & 127) * 32;
    const float* x = (isq ? x2 : x1);
    xs4[tid] = ((const float4*)(x + (size_t)lrow0 * DX_))[tid];
    __syncthreads();

    int trow = tid >> 4;
    int j    = tid & 15;
    float sgn = isq ? -1.f : 1.f;

    float a0 = bs[2*j], a1 = bs[2*j+1];
    float c0 = bs[2*j], c1 = bs[2*j+1];
    #pragma unroll
    for (int d4 = 0; d4 < DX_ / 4; d4++) {
        float4 xv = xs4[trow * (DX_ / 4) + d4];
        float4 yv = xs4[(trow + 16) * (DX_ / 4) + d4];
        float w0x = Ws[2*j][4*d4+0], w0y = Ws[2*j][4*d4+1];
        float w0z = Ws[2*j][4*d4+2], w0w = Ws[2*j][4*d4+3];
        float w1x = Ws[2*j+1][4*d4+0], w1y = Ws[2*j+1][4*d4+1];
        float w1z = Ws[2*j+1][4*d4+2], w1w = Ws[2*j+1][4*d4+3];
        a0 = fmaf(xv.x, w0x, a0); a0 = fmaf(xv.y, w0y, a0);
        a0 = fmaf(xv.z, w0z, a0); a0 = fmaf(xv.w, w0w, a0);
        a1 = fmaf(xv.x, w1x, a1); a1 = fmaf(xv.y, w1y, a1);
        a1 = fmaf(xv.z, w1z, a1); a1 = fmaf(xv.w, w1w, a1);
        c0 = fmaf(yv.x, w0x, c0); c0 = fmaf(yv.y, w0y, c0);
        c0 = fmaf(yv.z, w0z, c0); c0 = fmaf(yv.w, w0w, c0);
        c1 = fmaf(yv.x, w1x, c1); c1 = fmaf(yv.y, w1y, c1);
        c1 = fmaf(yv.z, w1z, c1); c1 = fmaf(yv.w, w1w, c1);
    }
    a0 *= sgn; a1 *= sgn; c0 *= sgn; c1 *= sgn;
    float pa = a0 + a1, pc = c0 + c1;

    int lrowA = lrow0 + trow, lrowC = lrow0 + trow + 16;
    ((float2*)((isq ? g_qfn : g_kf) + (size_t)lrowA * H_))[j] = make_float2(a0, a1);
    ((float2*)((isq ? g_qfn : g_kf) + (size_t)lrowC * H_))[j] = make_float2(c0, c1);

    if (isq) {
        g_q2n[(size_t)lrowA * NPAIR + j] = pa;
        g_q2n[(size_t)lrowC * NPAIR + j] = pc;
    } else {
        ktps[j][trow]      = pa;
        ktps[j][trow + 16] = pc;
        __syncthreads();
        int w    = tid >> 5;
        int lane = tid & 31;
        int batch = lrow0 >> 10, n0 = lrow0 & (N_ - 1);
        ull v = pk2(ktps[2*w][lane], ktps[2*w+1][lane]);
        g_k2t[((size_t)batch * 8 + w) * N_ + n0 + lane] = v;
    }
}

// ---------------------------------------------------------------------------
// fill: out[b][m][v] = w_sat * S[b][v]
// ---------------------------------------------------------------------------
__global__ __launch_bounds__(256) void fill_kernel(float* __restrict__ out) {
    __shared__ float Ssm[DV_];
    int blk = blockIdx.x, tid = threadIdx.x;
    int batch = blk >> 4, grp = blk & 15;

    const float w_sat = 1.0f + xla_fast_tanh(-XLA_TANH_CLAMP);

    if (tid < DV_) {
        const float* Sp = g_Sp + (size_t)batch * 16 * DV_;
        float S = 0.f;
        #pragma unroll
        for (int p = 0; p < 16; p++) S += Sp[p * DV_ + tid];
        Ssm[tid] = w_sat * S;
    }
    __syncthreads();

    float4* op = (float4*)(out + ((size_t)batch * M_ + grp * 64) * DV_);
    #pragma unroll
    for (int i = 0; i < 4; i++) {
        int idx = tid + i * 256;
        int v4 = idx & 15;
        op[idx] = make_float4(Ssm[4*v4+0], Ssm[4*v4+1], Ssm[4*v4+2], Ssm[4*v4+3]);
    }
}

// ---------------------------------------------------------------------------
// Cold path (deferred): exact s from stored projections; atomic correction.
// ---------------------------------------------------------------------------
__device__ __noinline__ void fix_pair(
    float* __restrict__ out_row, const float* __restrict__ r_in,
    int batch, int m, int n, float w_sat
) {
    const float4* kp = (const float4*)(g_kf  + ((size_t)batch * N_ + n) * H_);
    const float4* qp = (const float4*)(g_qfn + ((size_t)batch * M_ + m) * H_);
    float s = 0.f;
    #pragma unroll
    for (int i = 0; i < H_ / 4; i++) {
        float4 a = kp[i], b = qp[i];   // b is already -q
        s += fabsf(a.x + b.x) + fabsf(a.y + b.y)
           + fabsf(a.z + b.z) + fabsf(a.w + b.w);
    }
    if (s < XLA_TANH_CLAMP) {
        float wv = 1.0f + xla_fast_tanh(-s);
        float delta = wv - w_sat;
        if (delta != 0.f) {
            const float* rp = r_in + ((size_t)batch * N_ + n) * DV_;
            for (int v = 0; v < DV_; v++) atomicAdd(&out_row[v], delta * rp[v]);
        }
    }
}

// ---------------------------------------------------------------------------
// attn: grid 1024 = B x (M/16) x 4 n-slices. 128 threads = 4 warps x 4 m-rows.
// 2-group unrolled pipeline (no buffer copies) + 6 CTAs/SM occupancy.
// Pair-sum lower bound >= clamp ==> w == w_sat exactly. Rare flags fixed
// after mainloop via atomics into out.
// ---------------------------------------------------------------------------
#define TM      16
#define NSLICE  4
#define NSEG    (N_ / NSLICE)       // 256 n per CTA
#define NGRP    (NSEG / 32)         // 8 groups (even)

__global__ __launch_bounds__(128, 6) void attn_kernel(
    const float* __restrict__ r_in,
    float* __restrict__ out
) {
    int tid   = threadIdx.x;
    int warp  = tid >> 5;
    int lane  = tid & 31;
    int bid   = blockIdx.x;
    int batch = bid >> 8;               // 256 units per batch
    int rem   = bid & 255;
    int mtile = rem >> 2;               // 64 m-tiles
    int slice = rem & 3;
    int m0    = mtile * TM + warp * 4;  // warp's 4 m rows
    int nbase = slice * NSEG;

    const float w_sat = 1.0f + xla_fast_tanh(-XLA_TANH_CLAMP);

    // negated q pair-sums for 4 rows (8 ull each; warp-uniform rows)
    ull nq[4][8];
    #pragma unroll
    for (int r = 0; r < 4; r++) {
        const ull* qr = (const ull*)(g_q2n + ((size_t)batch * M_ + m0 + r) * NPAIR);
        #pragma unroll
        for (int i = 0; i < 8; i++) nq[r][i] = qr[i];
    }

    const ull* kt = g_k2t + (size_t)batch * 8 * N_ + nbase + lane;   // [i][n]

    unsigned mask[4] = {0, 0, 0, 0};    // NGRP bits per row

    // bound for one group's loaded data against all 4 rows
    auto bound4 = [&](const ull* kv, int g) {
        ull acc[4][2];
        #pragma unroll
        for (int r = 0; r < 4; r++) { acc[r][0] = 0; acc[r][1] = 0; }
        #pragma unroll
        for (int i = 0; i < 8; i++)
            #pragma unroll
            for (int r = 0; r < 4; r++) {
                ull d = add2(kv[i], nq[r][i]) & ABS2_MASK;
                acc[r][i & 1] = add2(acc[r][i & 1], d);
            }
        #pragma unroll
        for (int r = 0; r < 4; r++) {
            float s = hsum2(add2(acc[r][0], acc[r][1]));  // lower bound s(m0+r, n)
            if (s < XLA_TANH_CLAMP) mask[r] |= 1u << g;
        }
    };

    // ---- 2-group unrolled software pipeline (no inter-buffer copies) ----
    ull kv[8], kw[8];
    #pragma unroll
    for (int i = 0; i < 8; i++) kv[i] = kt[(size_t)i * N_];   // group 0

    #pragma unroll 1
    for (int g = 0; g < NGRP; g += 2) {
        {   // prefetch g+1, compute g (from kv)
            size_t off = (size_t)(g + 1) * 32;
            #pragma unroll
            for (int i = 0; i < 8; i++) kw[i] = kt[(size_t)i * N_ + off];
        }
        bound4(kv, g);
        if (g + 2 < NGRP) {   // prefetch g+2, compute g+1 (from kw)
            size_t off = (size_t)(g + 2) * 32;
            #pragma unroll
            for (int i = 0; i < 8; i++) kv[i] = kt[(size_t)i * N_ + off];
        }
        bound4(kw, g + 1);
    }

    // Deferred rare path: exact recompute + atomic correction into out.
    #pragma unroll
    for (int r = 0; r < 4; r++) {
        unsigned mk = mask[r];
        while (mk) {
            int g = __ffs(mk) - 1; mk &= mk - 1;
            int n = nbase + g * 32 + lane;
            fix_pair(out + ((size_t)batch * M_ + m0 + r) * DV_, r_in,
                     batch, m0 + r, n, w_sat);
        }
    }
}

// ---------------------------------------------------------------------------
// Launch: bind inputs by element count (robust to metadata ordering).
// ---------------------------------------------------------------------------
extern "C" void kernel_launch(void* const* d_in, const int* in_sizes, int n_in,
                              void* d_out, int out_size) {
    const float* x1 = nullptr;
    const float* x2 = nullptr;
    const float* r  = nullptr;
    const float* W  = nullptr;
    const float* b  = nullptr;

    for (int i = 0; i < n_in; i++) {
        int sz = in_sizes[i];
        const float* p = (const float*)d_in[i];
        if (sz == B_ * N_ * DV_)      { r = p; }
        else if (sz == H_ * DX_)      { W = p; }
        else if (sz == H_)            { b = p; }
        else if (sz == B_ * N_ * DX_) { if (!x1) x1 = p; else x2 = p; }
    }
    if (!x1 || !x2 || !r || !W || !b) {
        x1 = (const float*)d_in[0];
        x2 = (const float*)d_in[1];
        r  = (const float*)d_in[2];
        W  = (const float*)d_in[3];
        b  = (const float*)d_in[4];
    }

    float* out = (float*)d_out;
    (void)out_size;

    prep_kernel<<<320, 256>>>(x1, x2, r, W, b);      // Sp, kf, qfn, k2t, q2n
    fill_kernel<<<64, 256>>>(out);                   // out = w_sat * S
    attn_kernel<<<B_ * (M_ / TM) * NSLICE, 128>>>(r, out);  // rare corrections
}

// round 16
// speedup vs baseline: 1.1977x; 1.1977x over previous
#include <cuda_runtime.h>

// Problem constants (fixed shapes per reference)
#define B_    4
#define M_    1024
#define N_    1024
#define DX_   32
#define H_    32
#define DV_   64
#define NPAIR 16      // H_/2 pair-sums per row

#define XLA_TANH_CLAMP 7.99881172180175781f

typedef unsigned long long ull;

// Scratch (no cudaMalloc allowed)
__device__ __align__(16) ull   g_k2t[B_ * 8 * N_];      // TRANSPOSED k pair-sums: [b][i][n] (ull = pairs 2i,2i+1)
__device__ __align__(16) float g_q2n[B_ * M_ * NPAIR];  // NEGATED pair sums of q (row-major)
__device__ __align__(16) float g_kf [B_ * N_ * H_];     // full k projection
__device__ __align__(16) float g_qfn[B_ * M_ * H_];     // NEGATED full q projection
__device__ __align__(16) float g_Sp [B_ * 16 * DV_];    // partial sums of r over n (16/batch)

// ---------------------------------------------------------------------------
// XLA EmitFastTanh (f32, with_fma=true) — bit-faithful replica.
// ---------------------------------------------------------------------------
__device__ __forceinline__ float xla_fast_tanh(float x) {
    float xc = fminf(fmaxf(x, -XLA_TANH_CLAMP), XLA_TANH_CLAMP);
    float x2 = xc * xc;
    float p = fmaf(x2, -2.76076847742355e-16f, 2.00018790482477e-13f);
    p = fmaf(x2, p, -8.60467152213735e-11f);
    p = fmaf(x2, p, 5.12229709037114e-08f);
    p = fmaf(x2, p, 1.48572235717979e-05f);
    p = fmaf(x2, p, 6.37261928875436e-04f);
    p = fmaf(x2, p, 4.89352455891786e-03f);
    p = xc * p;
    float q = fmaf(x2, 1.19825839466702e-06f, 1.18534705686654e-04f);
    q = fmaf(x2, q, 2.26843463243900e-03f);
    q = fmaf(x2, q, 4.89352518554385e-03f);
    float t = p / q;                  // IEEE div.rn
    if (fabsf(x) < 0.0004f) t = x;
    return t;
}

// Packed f32x2 helpers
__device__ __forceinline__ ull add2(ull a, ull b) {
    ull d;
    asm("add.rn.f32x2 %0, %1, %2;" : "=l"(d) : "l"(a), "l"(b));
    return d;
}
__device__ __forceinline__ float hsum2(ull a) {
    float lo, hi;
    asm("mov.b64 {%0, %1}, %2;" : "=f"(lo), "=f"(hi) : "l"(a));
    return lo + hi;
}
__device__ __forceinline__ ull pk2(float lo, float hi) {
    ull r;
    asm("mov.b64 %0, {%1, %2};" : "=l"(r) : "f"(lo), "f"(hi));
    return r;
}
#define ABS2_MASK 0x7FFFFFFF7FFFFFFFULL

// ---------------------------------------------------------------------------
// prep: 320 blocks x 256 threads.  (EXACT R12 version — best measured)
//  blocks   0..63  : r column-sum partials (16/batch, 64 n each) -> g_Sp.
//  blocks  64..191 : k projections (x1), 32 rows/block -> g_kf + g_k2t
//                    (k2t via SMEM transpose -> coalesced STG.64).
//  blocks 192..319 : q projections NEGATED (x2), 32 rows/block -> g_qfn+g_q2n.
//  Ws padded to DX_+1: lane banks (2j+d) mod 32 are conflict-free.
// ---------------------------------------------------------------------------
__global__ __launch_bounds__(256) void prep_kernel(
    const float* __restrict__ x1,
    const float* __restrict__ x2,
    const float* __restrict__ r_in,
    const float* __restrict__ W,
    const float* __restrict__ bias
) {
    int blk = blockIdx.x, tid = threadIdx.x;

    if (blk < 64) {
        __shared__ float ps[4][DV_];
        int batch = blk >> 4, part = blk & 15;
        int v = tid & 63, sub = tid >> 6;           // 4 subs x 16 n
        const float* rp = r_in + ((size_t)batch * N_ + part * 64 + sub * 16) * DV_ + v;
        float s = 0.f;
        #pragma unroll
        for (int n = 0; n < 16; n++) s += rp[n * DV_];
        ps[sub][v] = s;
        __syncthreads();
        if (tid < DV_)
            g_Sp[((size_t)batch * 16 + part) * DV_ + tid] =
                (ps[0][tid] + ps[1][tid]) + (ps[2][tid] + ps[3][tid]);
        return;
    }

    __shared__ float  Ws[H_][DX_ + 1];
    __shared__ float  bs[H_];
    __shared__ float4 xs4[32 * (DX_ / 4)];
    __shared__ float  ktps[NPAIR][33];

    for (int i = tid; i < H_ * DX_; i += 256) {
        int h = i >> 5, d = i & 31;
        Ws[h][d] = W[i];
    }
    if (tid < H_) bs[tid] = bias[tid];

    int isq   = (blk >= 192);
    int lrow0 = ((blk - 64) & 127) * 32;
    const float* x = (isq ? x2 : x1);
    xs4[tid] = ((const float4*)(x + (size_t)lrow0 * DX_))[tid];
    __syncthreads();

    int trow = tid >> 4;
    int j    = tid & 15;
    float sgn = isq ? -1.f : 1.f;

    float a0 = bs[2*j], a1 = bs[2*j+1];
    float c0 = bs[2*j], c1 = bs[2*j+1];
    #pragma unroll
    for (int d4 = 0; d4 < DX_ / 4; d4++) {
        float4 xv = xs4[trow * (DX_ / 4) + d4];
        float4 yv = xs4[(trow + 16) * (DX_ / 4) + d4];
        float w0x = Ws[2*j][4*d4+0], w0y = Ws[2*j][4*d4+1];
        float w0z = Ws[2*j][4*d4+2], w0w = Ws[2*j][4*d4+3];
        float w1x = Ws[2*j+1][4*d4+0], w1y = Ws[2*j+1][4*d4+1];
        float w1z = Ws[2*j+1][4*d4+2], w1w = Ws[2*j+1][4*d4+3];
        a0 = fmaf(xv.x, w0x, a0); a0 = fmaf(xv.y, w0y, a0);
        a0 = fmaf(xv.z, w0z, a0); a0 = fmaf(xv.w, w0w, a0);
        a1 = fmaf(xv.x, w1x, a1); a1 = fmaf(xv.y, w1y, a1);
        a1 = fmaf(xv.z, w1z, a1); a1 = fmaf(xv.w, w1w, a1);
        c0 = fmaf(yv.x, w0x, c0); c0 = fmaf(yv.y, w0y, c0);
        c0 = fmaf(yv.z, w0z, c0); c0 = fmaf(yv.w, w0w, c0);
        c1 = fmaf(yv.x, w1x, c1); c1 = fmaf(yv.y, w1y, c1);
        c1 = fmaf(yv.z, w1z, c1); c1 = fmaf(yv.w, w1w, c1);
    }
    a0 *= sgn; a1 *= sgn; c0 *= sgn; c1 *= sgn;
    float pa = a0 + a1, pc = c0 + c1;

    int lrowA = lrow0 + trow, lrowC = lrow0 + trow + 16;
    ((float2*)((isq ? g_qfn : g_kf) + (size_t)lrowA * H_))[j] = make_float2(a0, a1);
    ((float2*)((isq ? g_qfn : g_kf) + (size_t)lrowC * H_))[j] = make_float2(c0, c1);

    if (isq) {
        g_q2n[(size_t)lrowA * NPAIR + j] = pa;
        g_q2n[(size_t)lrowC * NPAIR + j] = pc;
    } else {
        ktps[j][trow]      = pa;
        ktps[j][trow + 16] = pc;
        __syncthreads();
        int w    = tid >> 5;
        int lane = tid & 31;
        int batch = lrow0 >> 10, n0 = lrow0 & (N_ - 1);
        ull v = pk2(ktps[2*w][lane], ktps[2*w+1][lane]);
        g_k2t[((size_t)batch * 8 + w) * N_ + n0 + lane] = v;
    }
}

// ---------------------------------------------------------------------------
// fill: out[b][m][v] = w_sat * S[b][v]
// ---------------------------------------------------------------------------
__global__ __launch_bounds__(256) void fill_kernel(float* __restrict__ out) {
    __shared__ float Ssm[DV_];
    int blk = blockIdx.x, tid = threadIdx.x;
    int batch = blk >> 4, grp = blk & 15;

    const float w_sat = 1.0f + xla_fast_tanh(-XLA_TANH_CLAMP);

    if (tid < DV_) {
        const float* Sp = g_Sp + (size_t)batch * 16 * DV_;
        float S = 0.f;
        #pragma unroll
        for (int p = 0; p < 16; p++) S += Sp[p * DV_ + tid];
        Ssm[tid] = w_sat * S;
    }
    __syncthreads();

    float4* op = (float4*)(out + ((size_t)batch * M_ + grp * 64) * DV_);
    #pragma unroll
    for (int i = 0; i < 4; i++) {
        int idx = tid + i * 256;
        int v4 = idx & 15;
        op[idx] = make_float4(Ssm[4*v4+0], Ssm[4*v4+1], Ssm[4*v4+2], Ssm[4*v4+3]);
    }
}

// ---------------------------------------------------------------------------
// Cold path (deferred): exact s from stored projections; atomic correction.
// ---------------------------------------------------------------------------
__device__ __noinline__ void fix_pair(
    float* __restrict__ out_row, const float* __restrict__ r_in,
    int batch, int m, int n, float w_sat
) {
    const float4* kp = (const float4*)(g_kf  + ((size_t)batch * N_ + n) * H_);
    const float4* qp = (const float4*)(g_qfn + ((size_t)batch * M_ + m) * H_);
    float s = 0.f;
    #pragma unroll
    for (int i = 0; i < H_ / 4; i++) {
        float4 a = kp[i], b = qp[i];   // b is already -q
        s += fabsf(a.x + b.x) + fabsf(a.y + b.y)
           + fabsf(a.z + b.z) + fabsf(a.w + b.w);
    }
    if (s < XLA_TANH_CLAMP) {
        float wv = 1.0f + xla_fast_tanh(-s);
        float delta = wv - w_sat;
        if (delta != 0.f) {
            const float* rp = r_in + ((size_t)batch * N_ + n) * DV_;
            for (int v = 0; v < DV_; v++) atomicAdd(&out_row[v], delta * rp[v]);
        }
    }
}

// ---------------------------------------------------------------------------
// attn: grid 1024 = B x (M/16) x 4 n-slices. 128 threads = 4 warps x 4 m-rows.
// EXACT R12 body (copy-based 2-stage pipeline, 80 regs). Only change:
// __launch_bounds__(128, 5) -> reg cap 102 (>= 80, no spill possible),
// 5 CTAs/SM = 20 warps/SM, 1.38 waves.
// ---------------------------------------------------------------------------
#define TM      16
#define NSLICE  4
#define NSEG    (N_ / NSLICE)       // 256 n per CTA
#define NGRP    (NSEG / 32)         // 8 groups

__global__ __launch_bounds__(128, 5) void attn_kernel(
    const float* __restrict__ r_in,
    float* __restrict__ out
) {
    int tid   = threadIdx.x;
    int warp  = tid >> 5;
    int lane  = tid & 31;
    int bid   = blockIdx.x;
    int batch = bid >> 8;               // 256 units per batch
    int rem   = bid & 255;
    int mtile = rem >> 2;               // 64 m-tiles
    int slice = rem & 3;
    int m0    = mtile * TM + warp * 4;  // warp's 4 m rows
    int nbase = slice * NSEG;

    const float w_sat = 1.0f + xla_fast_tanh(-XLA_TANH_CLAMP);

    // negated q pair-sums for 4 rows (8 ull each; warp-uniform rows)
    ull nq[4][8];
    #pragma unroll
    for (int r = 0; r < 4; r++) {
        const ull* qr = (const ull*)(g_q2n + ((size_t)batch * M_ + m0 + r) * NPAIR);
        #pragma unroll
        for (int i = 0; i < 8; i++) nq[r][i] = qr[i];
    }

    const ull* kt = g_k2t + (size_t)batch * 8 * N_ + nbase + lane;   // [i][n]

    unsigned mask[4] = {0, 0, 0, 0};    // 8 group bits per row

    // ---- software pipeline over groups (R12 copy-based version) ----
    ull kv[8];
    #pragma unroll
    for (int i = 0; i < 8; i++) kv[i] = kt[(size_t)i * N_];   // group 0

    #pragma unroll 1
    for (int g = 0; g < NGRP; g++) {
        ull kw[8];
        if (g + 1 < NGRP) {
            size_t off = (size_t)(g + 1) * 32;
            #pragma unroll
            for (int i = 0; i < 8; i++) kw[i] = kt[(size_t)i * N_ + off];
        }

        ull acc[4][2];
        #pragma unroll
        for (int r = 0; r < 4; r++) { acc[r][0] = 0; acc[r][1] = 0; }
        #pragma unroll
        for (int i = 0; i < 8; i++)
            #pragma unroll
            for (int r = 0; r < 4; r++) {
                ull d = add2(kv[i], nq[r][i]) & ABS2_MASK;
                acc[r][i & 1] = add2(acc[r][i & 1], d);
            }
        #pragma unroll
        for (int r = 0; r < 4; r++) {
            float s = hsum2(add2(acc[r][0], acc[r][1]));  // lower bound s(m0+r, n)
            if (s < XLA_TANH_CLAMP) mask[r] |= 1u << g;
        }

        #pragma unroll
        for (int i = 0; i < 8; i++) kv[i] = kw[i];
    }

    // Deferred rare path: exact recompute + atomic correction into out.
    #pragma unroll
    for (int r = 0; r < 4; r++) {
        unsigned mk = mask[r];
        while (mk) {
            int g = __ffs(mk) - 1; mk &= mk - 1;
            int n = nbase + g * 32 + lane;
            fix_pair(out + ((size_t)batch * M_ + m0 + r) * DV_, r_in,
                     batch, m0 + r, n, w_sat);
        }
    }
}

// ---------------------------------------------------------------------------
// Launch: bind inputs by element count (robust to metadata ordering).
// ---------------------------------------------------------------------------
extern "C" void kernel_launch(void* const* d_in, const int* in_sizes, int n_in,
                              void* d_out, int out_size) {
    const float* x1 = nullptr;
    const float* x2 = nullptr;
    const float* r  = nullptr;
    const float* W  = nullptr;
    const float* b  = nullptr;

    for (int i = 0; i < n_in; i++) {
        int sz = in_sizes[i];
        const float* p = (const float*)d_in[i];
        if (sz == B_ * N_ * DV_)      { r = p; }
        else if (sz == H_ * DX_)      { W = p; }
        else if (sz == H_)            { b = p; }
        else if (sz == B_ * N_ * DX_) { if (!x1) x1 = p; else x2 = p; }
    }
    if (!x1 || !x2 || !r || !W || !b) {
        x1 = (const float*)d_in[0];
        x2 = (const float*)d_in[1];
        r  = (const float*)d_in[2];
        W  = (const float*)d_in[3];
        b  = (const float*)d_in[4];
    }

    float* out = (float*)d_out;
    (void)out_size;

    prep_kernel<<<320, 256>>>(x1, x2, r, W, b);      // Sp, kf, qfn, k2t, q2n
    fill_kernel<<<64, 256>>>(out);                   // out = w_sat * S
    attn_kernel<<<B_ * (M_ / TM) * NSLICE, 128>>>(r, out);  // rare corrections
}

// round 17
// speedup vs baseline: 1.5173x; 1.2669x over previous
#include <cuda_runtime.h>

// Problem constants (fixed shapes per reference)
#define B_    4
#define M_    1024
#define N_    1024
#define DX_   32
#define H_    32
#define DV_   64
#define NPAIR 16      // H_/2 pair-sums per row

#define XLA_TANH_CLAMP 7.99881172180175781f

typedef unsigned long long ull;

// Scratch (no cudaMalloc allowed)
__device__ __align__(16) ull   g_k2t[B_ * 8 * N_];      // TRANSPOSED k pair-sums: [b][i][n] (ull = pairs 2i,2i+1)
__device__ __align__(16) float g_q2n[B_ * M_ * NPAIR];  // NEGATED pair sums of q (row-major)
__device__ __align__(16) float g_kf [B_ * N_ * H_];     // full k projection
__device__ __align__(16) float g_qfn[B_ * M_ * H_];     // NEGATED full q projection
__device__ __align__(16) float g_Sp [B_ * 16 * DV_];    // partial sums of r over n (16/batch)

// ---------------------------------------------------------------------------
// XLA EmitFastTanh (f32, with_fma=true) — bit-faithful replica.
// ---------------------------------------------------------------------------
__device__ __forceinline__ float xla_fast_tanh(float x) {
    float xc = fminf(fmaxf(x, -XLA_TANH_CLAMP), XLA_TANH_CLAMP);
    float x2 = xc * xc;
    float p = fmaf(x2, -2.76076847742355e-16f, 2.00018790482477e-13f);
    p = fmaf(x2, p, -8.60467152213735e-11f);
    p = fmaf(x2, p, 5.12229709037114e-08f);
    p = fmaf(x2, p, 1.48572235717979e-05f);
    p = fmaf(x2, p, 6.37261928875436e-04f);
    p = fmaf(x2, p, 4.89352455891786e-03f);
    p = xc * p;
    float q = fmaf(x2, 1.19825839466702e-06f, 1.18534705686654e-04f);
    q = fmaf(x2, q, 2.26843463243900e-03f);
    q = fmaf(x2, q, 4.89352518554385e-03f);
    float t = p / q;                  // IEEE div.rn
    if (fabsf(x) < 0.0004f) t = x;
    return t;
}

// Packed f32x2 helpers
__device__ __forceinline__ ull add2(ull a, ull b) {
    ull d;
    asm("add.rn.f32x2 %0, %1, %2;" : "=l"(d) : "l"(a), "l"(b));
    return d;
}
__device__ __forceinline__ float hsum2(ull a) {
    float lo, hi;
    asm("mov.b64 {%0, %1}, %2;" : "=f"(lo), "=f"(hi) : "l"(a));
    return lo + hi;
}
__device__ __forceinline__ ull pk2(float lo, float hi) {
    ull r;
    asm("mov.b64 %0, {%1, %2};" : "=l"(r) : "f"(lo), "f"(hi));
    return r;
}
#define ABS2_MASK 0x7FFFFFFF7FFFFFFFULL

// ---------------------------------------------------------------------------
// prep: 320 blocks x 256 threads.  (EXACT R12 version — best measured)
//  blocks   0..63  : r column-sum partials (16/batch, 64 n each) -> g_Sp.
//  blocks  64..191 : k projections (x1), 32 rows/block -> g_kf + g_k2t
//                    (k2t via SMEM transpose -> coalesced STG.64).
//  blocks 192..319 : q projections NEGATED (x2), 32 rows/block -> g_qfn+g_q2n.
//  Ws padded to DX_+1: lane banks (2j+d) mod 32 are conflict-free.
// ---------------------------------------------------------------------------
__global__ __launch_bounds__(256) void prep_kernel(
    const float* __restrict__ x1,
    const float* __restrict__ x2,
    const float* __restrict__ r_in,
    const float* __restrict__ W,
    const float* __restrict__ bias
) {
    int blk = blockIdx.x, tid = threadIdx.x;

    if (blk < 64) {
        __shared__ float ps[4][DV_];
        int batch = blk >> 4, part = blk & 15;
        int v = tid & 63, sub = tid >> 6;           // 4 subs x 16 n
        const float* rp = r_in + ((size_t)batch * N_ + part * 64 + sub * 16) * DV_ + v;
        float s = 0.f;
        #pragma unroll
        for (int n = 0; n < 16; n++) s += rp[n * DV_];
        ps[sub][v] = s;
        __syncthreads();
        if (tid < DV_)
            g_Sp[((size_t)batch * 16 + part) * DV_ + tid] =
                (ps[0][tid] + ps[1][tid]) + (ps[2][tid] + ps[3][tid]);
        return;
    }

    __shared__ float  Ws[H_][DX_ + 1];
    __shared__ float  bs[H_];
    __shared__ float4 xs4[32 * (DX_ / 4)];
    __shared__ float  ktps[NPAIR][33];

    for (int i = tid; i < H_ * DX_; i += 256) {
        int h = i >> 5, d = i & 31;
        Ws[h][d] = W[i];
    }
    if (tid < H_) bs[tid] = bias[tid];

    int isq   = (blk >= 192);
    int lrow0 = ((blk - 64) & 127) * 32;
    const float* x = (isq ? x2 : x1);
    xs4[tid] = ((const float4*)(x + (size_t)lrow0 * DX_))[tid];
    __syncthreads();

    int trow = tid >> 4;
    int j    = tid & 15;
    float sgn = isq ? -1.f : 1.f;

    float a0 = bs[2*j], a1 = bs[2*j+1];
    float c0 = bs[2*j], c1 = bs[2*j+1];
    #pragma unroll
    for (int d4 = 0; d4 < DX_ / 4; d4++) {
        float4 xv = xs4[trow * (DX_ / 4) + d4];
        float4 yv = xs4[(trow + 16) * (DX_ / 4) + d4];
        float w0x = Ws[2*j][4*d4+0], w0y = Ws[2*j][4*d4+1];
        float w0z = Ws[2*j][4*d4+2], w0w = Ws[2*j][4*d4+3];
        float w1x = Ws[2*j+1][4*d4+0], w1y = Ws[2*j+1][4*d4+1];
        float w1z = Ws[2*j+1][4*d4+2], w1w = Ws[2*j+1][4*d4+3];
        a0 = fmaf(xv.x, w0x, a0); a0 = fmaf(xv.y, w0y, a0);
        a0 = fmaf(xv.z, w0z, a0); a0 = fmaf(xv.w, w0w, a0);
        a1 = fmaf(xv.x, w1x, a1); a1 = fmaf(xv.y, w1y, a1);
        a1 = fmaf(xv.z, w1z, a1); a1 = fmaf(xv.w, w1w, a1);
        c0 = fmaf(yv.x, w0x, c0); c0 = fmaf(yv.y, w0y, c0);
        c0 = fmaf(yv.z, w0z, c0); c0 = fmaf(yv.w, w0w, c0);
        c1 = fmaf(yv.x, w1x, c1); c1 = fmaf(yv.y, w1y, c1);
        c1 = fmaf(yv.z, w1z, c1); c1 = fmaf(yv.w, w1w, c1);
    }
    a0 *= sgn; a1 *= sgn; c0 *= sgn; c1 *= sgn;
    float pa = a0 + a1, pc = c0 + c1;

    int lrowA = lrow0 + trow, lrowC = lrow0 + trow + 16;
    ((float2*)((isq ? g_qfn : g_kf) + (size_t)lrowA * H_))[j] = make_float2(a0, a1);
    ((float2*)((isq ? g_qfn : g_kf) + (size_t)lrowC * H_))[j] = make_float2(c0, c1);

    if (isq) {
        g_q2n[(size_t)lrowA * NPAIR + j] = pa;
        g_q2n[(size_t)lrowC * NPAIR + j] = pc;
    } else {
        ktps[j][trow]      = pa;
        ktps[j][trow + 16] = pc;
        __syncthreads();
        int w    = tid >> 5;
        int lane = tid & 31;
        int batch = lrow0 >> 10, n0 = lrow0 & (N_ - 1);
        ull v = pk2(ktps[2*w][lane], ktps[2*w+1][lane]);
        g_k2t[((size_t)batch * 8 + w) * N_ + n0 + lane] = v;
    }
}

// ---------------------------------------------------------------------------
// fill: out[b][m][v] = w_sat * S[b][v]
// ---------------------------------------------------------------------------
__global__ __launch_bounds__(256) void fill_kernel(float* __restrict__ out) {
    __shared__ float Ssm[DV_];
    int blk = blockIdx.x, tid = threadIdx.x;
    int batch = blk >> 4, grp = blk & 15;

    const float w_sat = 1.0f + xla_fast_tanh(-XLA_TANH_CLAMP);

    if (tid < DV_) {
        const float* Sp = g_Sp + (size_t)batch * 16 * DV_;
        float S = 0.f;
        #pragma unroll
        for (int p = 0; p < 16; p++) S += Sp[p * DV_ + tid];
        Ssm[tid] = w_sat * S;
    }
    __syncthreads();

    float4* op = (float4*)(out + ((size_t)batch * M_ + grp * 64) * DV_);
    #pragma unroll
    for (int i = 0; i < 4; i++) {
        int idx = tid + i * 256;
        int v4 = idx & 15;
        op[idx] = make_float4(Ssm[4*v4+0], Ssm[4*v4+1], Ssm[4*v4+2], Ssm[4*v4+3]);
    }
}

// ---------------------------------------------------------------------------
// Cold path (deferred): exact s from stored projections; atomic correction.
// ---------------------------------------------------------------------------
__device__ __noinline__ void fix_pair(
    float* __restrict__ out_row, const float* __restrict__ r_in,
    int batch, int m, int n, float w_sat
) {
    const float4* kp = (const float4*)(g_kf  + ((size_t)batch * N_ + n) * H_);
    const float4* qp = (const float4*)(g_qfn + ((size_t)batch * M_ + m) * H_);
    float s = 0.f;
    #pragma unroll
    for (int i = 0; i < H_ / 4; i++) {
        float4 a = kp[i], b = qp[i];   // b is already -q
        s += fabsf(a.x + b.x) + fabsf(a.y + b.y)
           + fabsf(a.z + b.z) + fabsf(a.w + b.w);
    }
    if (s < XLA_TANH_CLAMP) {
        float wv = 1.0f + xla_fast_tanh(-s);
        float delta = wv - w_sat;
        if (delta != 0.f) {
            const float* rp = r_in + ((size_t)batch * N_ + n) * DV_;
            for (int v = 0; v < DV_; v++) atomicAdd(&out_row[v], delta * rp[v]);
        }
    }
}

// ---------------------------------------------------------------------------
// attn: grid 1024 = B x (M/16) x 4 n-slices. 128 threads = 4 warps x 4 m-rows.
// EXACT R12 body: copy-based 2-stage pipeline, __launch_bounds__(128, 4)
// (cap 128 — full scheduling budget; actual 80 regs -> 6 CTAs/SM at runtime).
// Pair-sum lower bound >= clamp ==> w == w_sat exactly. Rare flags fixed
// after the mainloop with atomics into out.
// ---------------------------------------------------------------------------
#define TM      16
#define NSLICE  4
#define NSEG    (N_ / NSLICE)       // 256 n per CTA
#define NGRP    (NSEG / 32)         // 8 groups

__global__ __launch_bounds__(128, 4) void attn_kernel(
    const float* __restrict__ r_in,
    float* __restrict__ out
) {
    int tid   = threadIdx.x;
    int warp  = tid >> 5;
    int lane  = tid & 31;
    int bid   = blockIdx.x;
    int batch = bid >> 8;               // 256 units per batch
    int rem   = bid & 255;
    int mtile = rem >> 2;               // 64 m-tiles
    int slice = rem & 3;
    int m0    = mtile * TM + warp * 4;  // warp's 4 m rows
    int nbase = slice * NSEG;

    const float w_sat = 1.0f + xla_fast_tanh(-XLA_TANH_CLAMP);

    // negated q pair-sums for 4 rows (8 ull each; warp-uniform rows)
    ull nq[4][8];
    #pragma unroll
    for (int r = 0; r < 4; r++) {
        const ull* qr = (const ull*)(g_q2n + ((size_t)batch * M_ + m0 + r) * NPAIR);
        #pragma unroll
        for (int i = 0; i < 8; i++) nq[r][i] = qr[i];
    }

    const ull* kt = g_k2t + (size_t)batch * 8 * N_ + nbase + lane;   // [i][n]

    unsigned mask[4] = {0, 0, 0, 0};    // 8 group bits per row

    // ---- software pipeline over groups ----
    ull kv[8];
    #pragma unroll
    for (int i = 0; i < 8; i++) kv[i] = kt[(size_t)i * N_];   // group 0

    #pragma unroll 1
    for (int g = 0; g < NGRP; g++) {
        ull kw[8];
        if (g + 1 < NGRP) {
            size_t off = (size_t)(g + 1) * 32;
            #pragma unroll
            for (int i = 0; i < 8; i++) kw[i] = kt[(size_t)i * N_ + off];
        }

        ull acc[4][2];
        #pragma unroll
        for (int r = 0; r < 4; r++) { acc[r][0] = 0; acc[r][1] = 0; }
        #pragma unroll
        for (int i = 0; i < 8; i++)
            #pragma unroll
            for (int r = 0; r < 4; r++) {
                ull d = add2(kv[i], nq[r][i]) & ABS2_MASK;
                acc[r][i & 1] = add2(acc[r][i & 1], d);
            }
        #pragma unroll
        for (int r = 0; r < 4; r++) {
            float s = hsum2(add2(acc[r][0], acc[r][1]));  // lower bound s(m0+r, n)
            if (s < XLA_TANH_CLAMP) mask[r] |= 1u << g;
        }

        #pragma unroll
        for (int i = 0; i < 8; i++) kv[i] = kw[i];
    }

    // Deferred rare path: exact recompute + atomic correction into out.
    #pragma unroll
    for (int r = 0; r < 4; r++) {
        unsigned mk = mask[r];
        while (mk) {
            int g = __ffs(mk) - 1; mk &= mk - 1;
            int n = nbase + g * 32 + lane;
            fix_pair(out + ((size_t)batch * M_ + m0 + r) * DV_, r_in,
                     batch, m0 + r, n, w_sat);
        }
    }
}

// ---------------------------------------------------------------------------
// Launch: bind inputs by element count (robust to metadata ordering).
// ---------------------------------------------------------------------------
extern "C" void kernel_launch(void* const* d_in, const int* in_sizes, int n_in,
                              void* d_out, int out_size) {
    const float* x1 = nullptr;
    const float* x2 = nullptr;
    const float* r  = nullptr;
    const float* W  = nullptr;
    const float* b  = nullptr;

    for (int i = 0; i < n_in; i++) {
        int sz = in_sizes[i];
        const float* p = (const float*)d_in[i];
        if (sz == B_ * N_ * DV_)      { r = p; }
        else if (sz == H_ * DX_)      { W = p; }
        else if (sz == H_)            { b = p; }
        else if (sz == B_ * N_ * DX_) { if (!x1) x1 = p; else x2 = p; }
    }
    if (!x1 || !x2 || !r || !W || !b) {
        x1 = (const float*)d_in[0];
        x2 = (const float*)d_in[1];
        r  = (const float*)d_in[2];
        W  = (const float*)d_in[3];
        b  = (const float*)d_in[4];
    }

    float* out = (float*)d_out;
    (void)out_size;

    prep_kernel<<<320, 256>>>(x1, x2, r, W, b);      // Sp, kf, qfn, k2t, q2n
    fill_kernel<<<64, 256>>>(out);                   // out = w_sat * S
    attn_kernel<<<B_ * (M_ / TM) * NSLICE, 128>>>(r, out);  // rare corrections
}